// round 1
// baseline (speedup 1.0000x reference)
#include <cuda_runtime.h>

#define TT     2190
#define NWARM  365
#define NMAIN  1825
#define NG     10000
#define KER    15
#define PF     5
#define G3     (NG * 3)

__global__ void __launch_bounds__(128, 1)
hbv_kernel(const float* __restrict__ x, const float* __restrict__ par,
           float* __restrict__ out)
{
    int g = blockIdx.x * blockDim.x + threadIdx.x;
    if (g >= NG) return;

    // ---- load raw params (coalesced-ish, once) ----
    float raw[14];
    #pragma unroll
    for (int i = 0; i < 14; ++i) raw[i] = par[g * 14 + i];

    // ---- scale to physical ranges ----
    const float beta  = 1.0f   + raw[0]  * 5.0f;
    const float fc    = 50.0f  + raw[1]  * 950.0f;
    const float k0    = 0.05f  + raw[2]  * 0.85f;
    const float k1    = 0.01f  + raw[3]  * 0.49f;
    const float k2    = 0.001f + raw[4]  * 0.199f;
    const float lp    = 0.2f   + raw[5]  * 0.8f;
    const float pperc =          raw[6]  * 10.0f;
    const float uzl   =          raw[7]  * 100.0f;
    const float tt    = -2.5f  + raw[8]  * 5.0f;
    const float cfmax = 0.5f   + raw[9]  * 9.5f;
    const float cfr   =          raw[10] * 0.1f;
    const float cwh   =          raw[11] * 0.2f;
    const float aa    =          raw[12] * 2.9f + 0.1f;   // relu(a)+0.1, a>=0
    const float theta =          raw[13] * 6.5f + 0.5f;   // relu(b)+0.5, b>=0

    const float cfrcf    = cfr * cfmax;
    const float inv_fc   = 1.0f / fc;
    const float inv_lpfc = 1.0f / (lp * fc);
    const float itheta   = 1.0f / theta;
    const float am1      = aa - 1.0f;

    // ---- gamma unit hydrograph (gammaln & aa*log(theta) cancel in normalization) ----
    float uh[KER];
    float s = 0.0f;
    #pragma unroll
    for (int k = 0; k < KER; ++k) {
        float tk = (float)k + 0.5f;
        float w  = __expf(am1 * __logf(tk) - tk * itheta);
        uh[k] = w;
        s += w;
    }
    float inv_s = 1.0f / s;
    #pragma unroll
    for (int k = 0; k < KER; ++k) uh[k] *= inv_s;

    // ---- state ----
    float snowpack = 0.001f, meltwater = 0.001f, sm = 0.001f;
    float suz = 0.001f, slz = 0.001f;

    // ---- one HBV timestep ----
    auto step = [&](float precip, float pet, float tm) -> float {
        bool  warm = (tm >= tt);
        float rain = warm ? precip : 0.0f;
        float snow = warm ? 0.0f   : precip;
        snowpack += snow;
        float melt = fminf(fmaxf(cfmax * (tm - tt), 0.0f), snowpack);
        meltwater += melt;
        snowpack  -= melt;
        float refr = fminf(fmaxf(cfrcf * (tt - tm), 0.0f), meltwater);
        snowpack  += refr;
        meltwater -= refr;
        float to_soil = fmaxf(meltwater - cwh * snowpack, 0.0f);
        meltwater -= to_soil;
        float ratio = sm * inv_fc;                         // prev sm <= fc, > 0
        float sw    = fminf(__powf(ratio, beta), 1.0f);    // >= 0 always
        float rts      = rain + to_soil;
        float recharge = rts * sw;
        sm = sm + rts - recharge;
        float excess = fmaxf(sm - fc, 0.0f);
        sm -= excess;
        float ef = fminf(sm * inv_lpfc, 1.0f);             // >= 0 always
        float et = fminf(sm, pet * ef);
        sm = fmaxf(sm - et, 1e-5f);
        suz = suz + recharge + excess;
        float perc = fminf(suz, pperc);
        suz -= perc;
        float q0 = k0 * fmaxf(suz - uzl, 0.0f);
        suz -= q0;
        float q1 = k1 * suz;
        suz -= q1;
        slz += perc;
        float q2 = k2 * slz;
        slz -= q2;
        return q0 + q1 + q2;
    };

    // ---- input pointers + software prefetch ring (distance PF=5 steps) ----
    const float* __restrict__ xp = x + g * 3;
    float bp[PF], be[PF], bt[PF];
    #pragma unroll
    for (int i = 0; i < PF; ++i) {
        bp[i] = xp[i * G3 + 0];
        be[i] = xp[i * G3 + 1];
        bt[i] = xp[i * G3 + 2];
    }
    int       off    = PF * G3;
    const int offmax = TT * G3;

    // ---- warmup phase: 365 steps, no output (365 = 73 * PF) ----
    #pragma unroll 1
    for (int it = 0; it < NWARM / PF; ++it) {
        #pragma unroll
        for (int u = 0; u < PF; ++u) {
            float p = bp[u], e = be[u], tm = bt[u];
            // safe: off stays < (NWARM+PF)*G3 << offmax
            bp[u] = xp[off + 0];
            be[u] = xp[off + 1];
            bt[u] = xp[off + 2];
            off += G3;
            (void)step(p, e, tm);
        }
    }

    // ---- main phase: 1825 steps with fused 15-tap convolution (1825 = 365 * PF) ----
    float pend[KER];
    #pragma unroll
    for (int k = 0; k < KER; ++k) pend[k] = 0.0f;

    float* __restrict__ op = out + g;

    #pragma unroll 1
    for (int it = 0; it < NMAIN / PF; ++it) {
        #pragma unroll
        for (int u = 0; u < PF; ++u) {
            float p = bp[u], e = be[u], tm = bt[u];
            if (off < offmax) {
                bp[u] = xp[off + 0];
                be[u] = xp[off + 1];
                bt[u] = xp[off + 2];
            }
            off += G3;
            float q = step(p, e, tm);

            float o = fmaf(uh[0], q, pend[0]);
            #pragma unroll
            for (int k = 0; k < KER - 1; ++k)
                pend[k] = fmaf(uh[k + 1], q, pend[k + 1]);
            pend[KER - 1] = 0.0f;

            *op = o;
            op += NG;
        }
    }
}

extern "C" void kernel_launch(void* const* d_in, const int* in_sizes, int n_in,
                              void* d_out, int out_size)
{
    const float* x   = (const float*)d_in[0];   // (2190, 10000, 3) f32
    const float* par = (const float*)d_in[1];   // (10000, 14) f32
    float*       out = (float*)d_out;           // (1825, 10000, 1) f32

    hbv_kernel<<<(NG + 127) / 128, 128>>>(x, par, out);
}

// round 3
// speedup vs baseline: 1.0683x; 1.0683x over previous
#include <cuda_runtime.h>

#define TT     2190
#define NWARM  365
#define NMAIN  1825
#define NG     10000
#define KER    15
#define PF     5
#define G3     (NG * 3)
#define CH     25                       // 1825 = 73 * 25

// scratch (device globals: the sanctioned no-alloc workaround)
__device__ float g_q[NMAIN * NG];       // raw simulated discharge, 73 MB
__device__ float g_uh[KER * NG];        // per-cell unit hydrograph

// ---------------------------------------------------------------------------
// K0: gamma unit hydrograph per cell (gammaln & a*log(theta) cancel in norm)
// ---------------------------------------------------------------------------
__global__ void __launch_bounds__(256)
uh_kernel(const float* __restrict__ par)
{
    int g = blockIdx.x * blockDim.x + threadIdx.x;
    if (g >= NG) return;
    float a   = fmaf(par[g * 14 + 12], 2.9f, 0.1f);   // relu(a)+0.1
    float th  = fmaf(par[g * 14 + 13], 6.5f, 0.5f);   // relu(b)+0.5
    float am1 = a - 1.0f;
    float ith = 1.0f / th;

    float w[KER], s = 0.0f;
    #pragma unroll
    for (int k = 0; k < KER; ++k) {
        float tk = (float)k + 0.5f;
        w[k] = __expf(fmaf(am1, __logf(tk), -tk * ith));
        s += w[k];
    }
    float inv = 1.0f / s;
    #pragma unroll
    for (int k = 0; k < KER; ++k) g_uh[k * NG + g] = w[k] * inv;
}

// ---------------------------------------------------------------------------
// K1: the sequential HBV scan. One thread per cell. Latency/issue bound:
// minimize instructions + dependency chain per step. No conv, no guards.
// ---------------------------------------------------------------------------
__global__ void __launch_bounds__(128, 1)
hbv_scan_kernel(const float* __restrict__ x, const float* __restrict__ par)
{
    int g = blockIdx.x * blockDim.x + threadIdx.x;
    if (g >= NG) return;

    float raw[14];
    #pragma unroll
    for (int i = 0; i < 14; ++i) raw[i] = par[g * 14 + i];

    const float beta  = 1.0f   + raw[0]  * 5.0f;
    const float fc    = 50.0f  + raw[1]  * 950.0f;
    const float k0    = 0.05f  + raw[2]  * 0.85f;
    const float k1    = 0.01f  + raw[3]  * 0.49f;
    const float k2    = 0.001f + raw[4]  * 0.199f;
    const float lp    = 0.2f   + raw[5]  * 0.8f;
    const float pperc =          raw[6]  * 10.0f;
    const float uzl   =          raw[7]  * 100.0f;
    const float tt    = -2.5f  + raw[8]  * 5.0f;
    const float cfmax = 0.5f   + raw[9]  * 9.5f;
    const float cfr   =          raw[10] * 0.1f;
    const float cwh   =          raw[11] * 0.2f;

    const float mcf      = -cfmax * tt;        // d = fma(cfmax, tm, mcf)
    const float inv_fc   = 1.0f / fc;
    const float inv_lpfc = 1.0f / (lp * fc);
    const float omk1     = 1.0f - k1;
    const float omk2     = 1.0f - k2;

    float snowpack = 0.001f, meltwater = 0.001f, sm = 0.001f;
    float suz = 0.001f, slz = 0.001f;

    auto step = [&](float precip, float pet, float tm) -> float {
        float rain = (tm >= tt) ? precip : 0.0f;
        float snow = precip - rain;
        float d    = fmaf(cfmax, tm, mcf);                    // cfmax*(tm-tt)
        float sp1  = snowpack + snow;
        float melt = fminf(fmaxf(d, 0.0f), sp1);
        float mw1  = meltwater + melt;
        float refr = fminf(fmaxf(-cfr * d, 0.0f), mw1);       // cfr*cfmax*(tt-tm)
        float mw2  = mw1 - refr;
        float sp2  = sp1 - melt + refr;
        float ts   = fmaxf(fmaf(-cwh, sp2, mw2), 0.0f);       // to_soil
        meltwater  = mw2 - ts;
        snowpack   = sp2;
        float sw   = fminf(__powf(sm * inv_fc, beta), 1.0f);  // sm>0 always
        float rts  = rain + ts;
        float rech = rts * sw;
        float sm1  = fmaf(rts, 1.0f - sw, sm);                // sm + rts - rech
        float sm2  = fminf(sm1, fc);
        float exc  = sm1 - sm2;                               // max(sm1-fc,0)
        float ef   = fminf(sm2 * inv_lpfc, 1.0f);
        sm         = fmaxf(fmaf(-pet, ef, sm2), 1e-5f);       // sm - min(sm,pet*ef)
        float suz2 = suz + rech + exc;
        float perc = fminf(suz2, pperc);
        float suz3 = suz2 - perc;
        float q0   = k0 * fmaxf(suz3 - uzl, 0.0f);
        float suz4 = suz3 - q0;
        float q1   = k1 * suz4;
        suz        = suz4 * omk1;
        float slz1 = slz + perc;
        float q2   = k2 * slz1;
        slz        = slz1 * omk2;
        return (q0 + q1) + q2;
    };

    // input stream + software prefetch ring, distance PF steps
    const float* __restrict__ xp = x + g * 3;
    float bp[PF], be[PF], bt[PF];
    #pragma unroll
    for (int i = 0; i < PF; ++i) {
        bp[i] = xp[i * G3 + 0];
        be[i] = xp[i * G3 + 1];
        bt[i] = xp[i * G3 + 2];
    }
    int off = PF * G3;

    // ---- warmup: 365 steps (73 x 5), always prefetch (max load step 369) ----
    #pragma unroll 1
    for (int it = 0; it < NWARM / PF; ++it) {
        #pragma unroll
        for (int u = 0; u < PF; ++u) {
            float p = bp[u], e = be[u], tm = bt[u];
            bp[u] = xp[off + 0];
            be[u] = xp[off + 1];
            bt[u] = xp[off + 2];
            off += G3;
            (void)step(p, e, tm);
        }
    }

    // ---- main A: 1820 steps (364 x 5) with prefetch (last load = step 2189) ----
    float* __restrict__ qp = g_q + g;
    #pragma unroll 1
    for (int it = 0; it < (NMAIN - PF) / PF; ++it) {
        #pragma unroll
        for (int u = 0; u < PF; ++u) {
            float p = bp[u], e = be[u], tm = bt[u];
            bp[u] = xp[off + 0];
            be[u] = xp[off + 1];
            bt[u] = xp[off + 2];
            off += G3;
            *qp = step(p, e, tm);
            qp += NG;
        }
    }

    // ---- main B: final 5 steps, drain the ring, no prefetch ----
    #pragma unroll
    for (int u = 0; u < PF; ++u) {
        *qp = step(bp[u], be[u], bt[u]);
        qp += NG;
    }
}

// ---------------------------------------------------------------------------
// K2: 15-tap causal convolution, fully parallel. Thread = (cell, 25-step chunk).
// ---------------------------------------------------------------------------
__global__ void __launch_bounds__(256)
conv_kernel(float* __restrict__ out)
{
    int g = blockIdx.x * blockDim.x + threadIdx.x;
    if (g >= NG) return;
    int t0 = blockIdx.y * CH;

    float uh[KER];
    #pragma unroll
    for (int k = 0; k < KER; ++k) uh[k] = g_uh[k * NG + g];

    // history window: w[j] = q[t0-1-j] (zero-padded before t=0)
    float w[KER - 1];
    #pragma unroll
    for (int j = 0; j < KER - 1; ++j) {
        int t = t0 - 1 - j;
        w[j] = (t >= 0) ? g_q[t * NG + g] : 0.0f;
    }

    #pragma unroll
    for (int s = 0; s < CH; ++s) {
        float qn = g_q[(t0 + s) * NG + g];
        float o  = uh[0] * qn;
        #pragma unroll
        for (int j = 0; j < KER - 1; ++j)
            o = fmaf(uh[j + 1], w[j], o);
        out[(t0 + s) * NG + g] = o;
        #pragma unroll
        for (int j = KER - 2; j > 0; --j) w[j] = w[j - 1];
        w[0] = qn;
    }
}

// ---------------------------------------------------------------------------
extern "C" void kernel_launch(void* const* d_in, const int* in_sizes, int n_in,
                              void* d_out, int out_size)
{
    const float* x   = (const float*)d_in[0];   // (2190, 10000, 3) f32
    const float* par = (const float*)d_in[1];   // (10000, 14) f32
    float*       out = (float*)d_out;           // (1825, 10000, 1) f32

    uh_kernel<<<(NG + 255) / 256, 256>>>(par);
    hbv_scan_kernel<<<(NG + 127) / 128, 128>>>(x, par);
    conv_kernel<<<dim3((NG + 255) / 256, NMAIN / CH), 256>>>(out);
}